// round 15
// baseline (speedup 1.0000x reference)
#include <cuda_runtime.h>
#include <math.h>

#define B_DIM 256
#define N_DIM 256
#define D_DIM 512
#define MARGIN 0.5f
#define EPS_V 1e-6f
#define ROWS (B_DIM * N_DIM)           // 65536
#define BND ((size_t)ROWS * D_DIM)     // 33554432
#define GROWS 8

// ---- scratch (device globals; no allocation allowed) ----
__device__ float g_dp[ROWS];
__device__ float g_dn[ROWS];
__device__ float g_loss_partial[B_DIM];
__device__ int   g_neg_idx[B_DIM];
__device__ int   g_pos_idx[B_DIM];
__device__ int   g_valid_neg[B_DIM];
__device__ int   g_valid_pos[B_DIM];
__device__ int   g_perm[2][B_DIM];   // batch visit order, sorted by source idx
__device__ int   g_arrive;           // zero-init; reset by last block each call

// ============================================================
// Kernel 1: per-row L2 distances. Warp-per-row, streaming loads.
// ============================================================
__global__ __launch_bounds__(256) void dist_kernel(
    const float* __restrict__ anchor,
    const float* __restrict__ positive,
    const float* __restrict__ negative)
{
    const int row  = blockIdx.x * 8 + (threadIdx.x >> 5);
    const int lane = threadIdx.x & 31;

    const float4* a4 = (const float4*)(anchor   + (size_t)row * D_DIM);
    const float4* p4 = (const float4*)(positive + (size_t)row * D_DIM);
    const float4* n4 = (const float4*)(negative + (size_t)row * D_DIM);

    float4 av[4], pv[4], nv[4];
    #pragma unroll
    for (int i = 0; i < 4; i++) av[i] = __ldcs(&a4[lane + 32 * i]);
    #pragma unroll
    for (int i = 0; i < 4; i++) pv[i] = __ldcs(&p4[lane + 32 * i]);
    #pragma unroll
    for (int i = 0; i < 4; i++) nv[i] = __ldcs(&n4[lane + 32 * i]);

    float dp = 0.0f, dn = 0.0f;
    #pragma unroll
    for (int i = 0; i < 4; i++) {
        float x0 = av[i].x - pv[i].x + EPS_V, x1 = av[i].y - pv[i].y + EPS_V;
        float x2 = av[i].z - pv[i].z + EPS_V, x3 = av[i].w - pv[i].w + EPS_V;
        dp += x0*x0 + x1*x1 + x2*x2 + x3*x3;
        float y0 = av[i].x - nv[i].x + EPS_V, y1 = av[i].y - nv[i].y + EPS_V;
        float y2 = av[i].z - nv[i].z + EPS_V, y3 = av[i].w - nv[i].w + EPS_V;
        dn += y0*y0 + y1*y1 + y2*y2 + y3*y3;
    }

    #pragma unroll
    for (int off = 16; off > 0; off >>= 1) {
        dp += __shfl_xor_sync(0xFFFFFFFFu, dp, off);
        dn += __shfl_xor_sync(0xFFFFFFFFu, dn, off);
    }

    if (lane == 0) {
        g_dp[row] = sqrtf(dp);
        g_dn[row] = sqrtf(dn);
    }
}

// ============================================================
// Kernel 2: mine + finalize (fused, last-block pattern).
// Each block mines its batch; the last-arriving block computes the
// loss sum and both scheduling perms. Deterministic: identical work
// regardless of which block arrives last.
// ============================================================
__global__ __launch_bounds__(256) void mine_finalize_kernel(float* __restrict__ out)
{
    const int b = blockIdx.x;
    const int n = threadIdx.x;

    // ---- mining for batch b ----
    {
        const float dp = g_dp[b * N_DIM + n];
        const float dn = g_dn[b * N_DIM + n];

        const bool mask_neg = (dp - dn + MARGIN) > 0.0f;
        const bool mask_pos = (dn - dp + MARGIN) > 0.0f;

        __shared__ float s_sn[N_DIM]; __shared__ int s_in[N_DIM];
        __shared__ float s_sp[N_DIM]; __shared__ int s_ip[N_DIM];
        __shared__ float s_ls[N_DIM];

        s_sn[n] = mask_neg ? dn : -INFINITY;  s_in[n] = n;
        s_sp[n] = mask_pos ? dp :  INFINITY;  s_ip[n] = n;
        s_ls[n] = fmaxf(0.0f, MARGIN + dp - dn);
        __syncthreads();

        for (int off = N_DIM / 2; off > 0; off >>= 1) {
            if (n < off) {
                float so = s_sn[n + off]; int io = s_in[n + off];
                if (so > s_sn[n] || (so == s_sn[n] && io < s_in[n])) {
                    s_sn[n] = so; s_in[n] = io;
                }
                float qo = s_sp[n + off]; int jo = s_ip[n + off];
                if (qo < s_sp[n] || (qo == s_sp[n] && jo < s_ip[n])) {
                    s_sp[n] = qo; s_ip[n] = jo;
                }
                s_ls[n] += s_ls[n + off];
            }
            __syncthreads();
        }

        if (n == 0) {
            const int vn = (s_sn[0] > -INFINITY) ? 1 : 0;
            const int vp = (s_sp[0] <  INFINITY) ? 1 : 0;
            g_neg_idx[b] = s_in[0];
            g_pos_idx[b] = s_ip[0];
            g_valid_neg[b] = vn;
            g_valid_pos[b] = vp;
            g_loss_partial[b] = s_ls[0];
            out[1 + 2 * BND + b]         = (float)vn;
            out[1 + 2 * BND + B_DIM + b] = (float)vp;
        }
        __syncthreads();
    }

    // ---- arrival; last block finalizes ----
    __shared__ int s_last;
    if (n == 0) {
        __threadfence();
        int old = atomicAdd(&g_arrive, 1);
        s_last = (old == B_DIM - 1) ? 1 : 0;
    }
    __syncthreads();
    if (!s_last) return;

    if (n == 0) g_arrive = 0;      // reset for next graph replay
    __threadfence();               // make all blocks' g_* visible

    // ---- loss sum ----
    __shared__ float s_l[B_DIM];
    s_l[n] = g_loss_partial[n];
    __syncthreads();
    for (int off = B_DIM / 2; off > 0; off >>= 1) {
        if (n < off) s_l[n] += s_l[n + off];
        __syncthreads();
    }
    if (n == 0) out[0] = s_l[0] * (1.0f / (float)(B_DIM * N_DIM));

    // ---- perms (counting sort by source index, both sides) ----
    __shared__ int s_cnt[B_DIM];
    __shared__ int s_a[B_DIM];
    __shared__ int s_b[B_DIM];
    __shared__ int s_cur[B_DIM];
    __shared__ int s_nvalid;

    for (int side = 0; side < 2; side++) {
        const int my_idx = (side == 0) ? g_neg_idx[n]   : g_pos_idx[n];
        const int my_val = (side == 0) ? g_valid_neg[n] : g_valid_pos[n];

        s_cnt[n] = 0;
        __syncthreads();
        if (my_val) atomicAdd(&s_cnt[my_idx], 1);
        __syncthreads();

        {
            const int v = s_cnt[n];
            s_a[n] = v;
            __syncthreads();
            int* cur = s_a; int* nxt = s_b;
            for (int d = 1; d < B_DIM; d <<= 1) {
                nxt[n] = (n >= d) ? (cur[n] + cur[n - d]) : cur[n];
                __syncthreads();
                int* tmp = cur; cur = nxt; nxt = tmp;
            }
            s_cur[n] = cur[n] - v;
            if (n == B_DIM - 1) s_nvalid = cur[n];
            __syncthreads();
        }

        if (my_val) {
            int p = atomicAdd(&s_cur[my_idx], 1);
            g_perm[side][p] = n;
        }
        __syncthreads();

        {
            const int inv = my_val ? 0 : 1;
            s_a[n] = inv;
            __syncthreads();
            int* cur = s_a; int* nxt = s_b;
            for (int d = 1; d < B_DIM; d <<= 1) {
                nxt[n] = (n >= d) ? (cur[n] + cur[n - d]) : cur[n];
                __syncthreads();
                int* tmp = cur; cur = nxt; nxt = tmp;
            }
            if (inv) g_perm[side][s_nvalid + cur[n] - 1] = n;
            __syncthreads();
        }
    }
}

// ============================================================
// Kernel 3: gather via cp.async staging + warp-local realignment.
// Block = (batch-position, n-group of 8, side); dest batch =
// g_perm[side][pos]. 16KB tile staged global->smem with cp.async
// (in-flight data lives in smem, not registers). Each warp owns 2
// rows: LDS.128 the 4 chunks, build the +3-shifted store vector with
// one rotate-shuffle ((lane+1)&31; lane 0 supplies its next chunk),
// store 127 STG.128 + head(0,1,2)/tail(511) scalars per row.
// ============================================================
__global__ __launch_bounds__(128) void gather_kernel(
    const float* __restrict__ positive,
    const float* __restrict__ negative,
    float* __restrict__ out)
{
    const int pos  = blockIdx.x;
    const int n0   = blockIdx.y * GROWS;
    const int side = blockIdx.z;
    const int t    = threadIdx.x;
    const int lane = t & 31;
    const int wid  = t >> 5;

    const int b = g_perm[side][pos];
    const int valid = (side == 0) ? g_valid_neg[b] : g_valid_pos[b];
    const int sidx  = (side == 0) ? g_neg_idx[b]   : g_pos_idx[b];

    const float4* __restrict__ src4 = (const float4*)(
        ((side == 0) ? negative : positive)
        + ((size_t)sidx * N_DIM + n0) * D_DIM);
    float* __restrict__ dst0 =
        out + 1 + (side ? BND : 0) + ((size_t)b * N_DIM + n0) * D_DIM;

    __shared__ float4 s_tile[GROWS * 128];   // 16 KB

    if (valid) {   // block-uniform predicate
        unsigned smbase = (unsigned)__cvta_generic_to_shared(&s_tile[0]);
        #pragma unroll
        for (int r = 0; r < GROWS; r++) {
            unsigned saddr = smbase + (unsigned)((r * 128 + t) * 16);
            const float4* gaddr = src4 + r * 128 + t;
            asm volatile("cp.async.cg.shared.global [%0], [%1], 16;"
                         :: "r"(saddr), "l"(gaddr));
        }
        asm volatile("cp.async.commit_group;");
        asm volatile("cp.async.wait_group 0;");
    }
    __syncthreads();

    // each warp realigns+stores rows 2*wid and 2*wid+1
    #pragma unroll
    for (int rr = 0; rr < 2; rr++) {
        const int r = 2 * wid + rr;
        float4 L[4];
        if (valid) {
            #pragma unroll
            for (int c = 0; c < 4; c++) L[c] = s_tile[r * 128 + 32 * c + lane];
        } else {
            #pragma unroll
            for (int c = 0; c < 4; c++) L[c] = make_float4(0.f, 0.f, 0.f, 0.f);
        }

        float* dst = dst0 + r * D_DIM;

        #pragma unroll
        for (int c = 0; c < 4; c++) {
            // lane l consumes from lane (l+1)&31; src lane 0 supplies its
            // NEXT chunk (serving consumer lane 31 of chunk c).
            float4 send = (lane == 0) ? ((c < 3) ? L[c + 1] : L[0]) : L[c];
            float nx = __shfl_sync(0xFFFFFFFFu, send.x, (lane + 1) & 31);
            float ny = __shfl_sync(0xFFFFFFFFu, send.y, (lane + 1) & 31);
            float nz = __shfl_sync(0xFFFFFFFFu, send.z, (lane + 1) & 31);
            const int j = 32 * c + lane;
            if (j < 127) {
                // dst + 3 + 4j is 16B-aligned (dst = out + 1 + 512*row)
                __stcs((float4*)(dst + 3 + 4 * j),
                       make_float4(L[c].w, nx, ny, nz));
            }
        }
        if (lane == 0) {
            dst[0] = L[0].x; dst[1] = L[0].y; dst[2] = L[0].z;
        }
        if (lane == 31) {
            dst[511] = L[3].w;
        }
    }
}

// ============================================================
extern "C" void kernel_launch(void* const* d_in, const int* in_sizes, int n_in,
                              void* d_out, int out_size)
{
    const float* anchor   = (const float*)d_in[0];
    const float* positive = (const float*)d_in[1];
    const float* negative = (const float*)d_in[2];
    float* out = (float*)d_out;

    dist_kernel         <<<ROWS / 8, 256>>>(anchor, positive, negative);
    mine_finalize_kernel<<<B_DIM, 256>>>(out);

    dim3 ggrid(B_DIM, N_DIM / GROWS, 2);
    gather_kernel<<<ggrid, 128>>>(positive, negative, out);
}